// round 3
// baseline (speedup 1.0000x reference)
#include <cuda_runtime.h>
#include <cstdint>

// ---------------- problem constants ----------------
#define HWPIX   (1024*1024)      // H*W
#define BATCH   4
#define CIN     3
#define NH      25               // MAXH
#define DEPTH   6

// Padded constant-weight layout (all entries are (w,w) duplicated into a u64):
//   win  : 25 rows x 4 slots   -> ull idx  o*4 + c            [0,   100)
//   ws   : 150 rows x 26 slots -> 100 + (d*25+o)*26 + c       [100, 4000)
//   wout : 3 rows x 26 slots   -> 4000 + o*26 + c             [4000,4078)
#define CW_ULLS 4078

__constant__ unsigned long long cW[CW_ULLS];
__device__   unsigned long long g_wdup[CW_ULLS];

// ---------------- f32x2 helpers (Blackwell packed fp32) ----------------
typedef unsigned long long ull;

__device__ __forceinline__ ull d_mul2(ull a, ull b) {
    ull d; asm("mul.rn.f32x2 %0, %1, %2;" : "=l"(d) : "l"(a), "l"(b)); return d;
}
__device__ __forceinline__ ull d_add2(ull a, ull b) {
    ull d; asm("add.rn.f32x2 %0, %1, %2;" : "=l"(d) : "l"(a), "l"(b)); return d;
}
__device__ __forceinline__ ull d_fma2(ull a, ull b, ull c) {
    ull d; asm("fma.rn.f32x2 %0, %1, %2, %3;" : "=l"(d) : "l"(a), "l"(b), "l"(c)); return d;
}
__device__ __forceinline__ void unpack2(ull v, float& a, float& b) {
    asm("mov.b64 {%0, %1}, %2;" : "=f"(a), "=f"(b) : "l"(v));
}
__device__ __forceinline__ ull pack2(float a, float b) {
    ull r; asm("mov.b64 %0, {%1, %2};" : "=l"(r) : "f"(a), "f"(b)); return r;
}
__device__ __forceinline__ ull bcast2(float f) {
    unsigned u = __float_as_uint(f);
    return ((ull)u << 32) | (ull)u;   // constant-folds for literals
}
__device__ __forceinline__ float d_ex2(float x) {
    float r; asm("ex2.approx.f32 %0, %1;" : "=f"(r) : "f"(x)); return r;
}
__device__ __forceinline__ float d_rcp(float x) {
    float r; asm("rcp.approx.f32 %0, %1;" : "=f"(r) : "f"(x)); return r;
}

// tanh on a pixel pair: tanh(x) = (e-1)/(e+1), e = 2^(x * 2*log2(e))
__device__ __forceinline__ ull tanh2(ull v) {
    ull s = d_mul2(v, bcast2(2.8853900817779268f));   // 2*log2(e)
    float s0, s1; unpack2(s, s0, s1);
    ull e   = pack2(d_ex2(s0), d_ex2(s1));
    ull num = d_add2(e, bcast2(-1.0f));
    ull den = d_add2(e, bcast2(1.0f));
    float dn0, dn1; unpack2(den, dn0, dn1);
    ull r = pack2(d_rcp(dn0), d_rcp(dn1));
    return d_mul2(num, r);
}

// sigmoid on a pixel pair: 1/(1 + 2^(-x*log2(e)))
__device__ __forceinline__ ull sigmoid2(ull v) {
    ull s = d_mul2(v, bcast2(-1.4426950408889634f));  // -log2(e)
    float s0, s1; unpack2(s, s0, s1);
    ull den = d_add2(pack2(d_ex2(s0), d_ex2(s1)), bcast2(1.0f));
    float dn0, dn1; unpack2(den, dn0, dn1);
    return pack2(d_rcp(dn0), d_rcp(dn1));
}

// ---------------- prep: duplicate weights into padded (w,w) layout ----------------
__global__ void prep_weights(const float* __restrict__ win,
                             const float* __restrict__ ws,
                             const float* __restrict__ wout) {
    int i = blockIdx.x * blockDim.x + threadIdx.x;
    if (i >= CW_ULLS) return;
    float w = 0.0f;
    if (i < 100) {
        int o = i >> 2, c = i & 3;
        if (c < CIN) w = win[o * CIN + c];
    } else if (i < 4000) {
        int j = i - 100;
        int row = j / 26, c = j % 26;           // row = d*25 + o
        if (c < NH) w = ws[row * NH + c];
    } else {
        int j = i - 4000;
        int o = j / 26, c = j % 26;
        if (c < NH) w = wout[o * NH + c];
    }
    unsigned u = __float_as_uint(w);
    g_wdup[i] = ((ull)u << 32) | (ull)u;
}

// ---------------- main kernel: one thread = one pixel pair ----------------
__global__ void __launch_bounds__(256)
simplenet_kernel(const float* __restrict__ x, float* __restrict__ out) {
    int t  = blockIdx.x * blockDim.x + threadIdx.x;   // pair index, 0..2097151
    int b  = t >> 19;                                 // HWPIX/2 = 2^19 pairs / image
    int hp = t & ((HWPIX >> 1) - 1);

    const float* xb = x + (size_t)b * (CIN * HWPIX) + ((size_t)hp << 1);

    // load 3 input channels for the pixel pair (coalesced 8B loads)
    ull x0 = *(const ull*)(xb);
    ull x1 = *(const ull*)(xb + HWPIX);
    ull x2 = *(const ull*)(xb + 2 * HWPIX);

    ull h[NH];

    // ---- input layer: 3 -> 25, tanh ----
    #pragma unroll
    for (int o = 0; o < NH; o++) {
        const int base = o * 4;
        ulonglong2 w01 = *(const ulonglong2*)&cW[base];   // LDC.128
        ull w2 = cW[base + 2];
        ull acc = d_mul2(w01.x, x0);
        acc = d_fma2(w01.y, x1, acc);
        acc = d_fma2(w2,    x2, acc);
        h[o] = tanh2(acc);
    }

    // ---- 6 hidden layers: 25 -> 25, tanh ----
    #pragma unroll 1
    for (int d = 0; d < DEPTH; d++) {
        ull hn[NH];
        const int lbase = 100 + d * (NH * 26);
        #pragma unroll
        for (int o = 0; o < NH; o++) {
            const int base = lbase + o * 26;
            ull a0, a1;
            {
                ulonglong2 w = *(const ulonglong2*)&cW[base];
                a0 = d_mul2(w.x, h[0]);
                a1 = d_mul2(w.y, h[1]);
            }
            #pragma unroll
            for (int cc = 1; cc < 12; cc++) {
                ulonglong2 w = *(const ulonglong2*)&cW[base + 2 * cc];
                a0 = d_fma2(w.x, h[2 * cc],     a0);
                a1 = d_fma2(w.y, h[2 * cc + 1], a1);
            }
            a0 = d_fma2(cW[base + 24], h[24], a0);
            hn[o] = tanh2(d_add2(a0, a1));
        }
        #pragma unroll
        for (int o = 0; o < NH; o++) h[o] = hn[o];
    }

    // ---- output layer: 25 -> 3, sigmoid ----
    float* ob = out + (size_t)b * (CIN * HWPIX) + ((size_t)hp << 1);
    #pragma unroll
    for (int o = 0; o < CIN; o++) {
        const int base = 4000 + o * 26;
        ull a0, a1;
        {
            ulonglong2 w = *(const ulonglong2*)&cW[base];
            a0 = d_mul2(w.x, h[0]);
            a1 = d_mul2(w.y, h[1]);
        }
        #pragma unroll
        for (int cc = 1; cc < 12; cc++) {
            ulonglong2 w = *(const ulonglong2*)&cW[base + 2 * cc];
            a0 = d_fma2(w.x, h[2 * cc],     a0);
            a1 = d_fma2(w.y, h[2 * cc + 1], a1);
        }
        a0 = d_fma2(cW[base + 24], h[24], a0);
        *(ull*)(ob + (size_t)o * HWPIX) = sigmoid2(d_add2(a0, a1));
    }
}

// ---------------- launch ----------------
extern "C" void kernel_launch(void* const* d_in, const int* in_sizes, int n_in,
                              void* d_out, int out_size) {
    const float* x    = (const float*)d_in[0];
    const float* win  = (const float*)d_in[1];
    const float* ws   = (const float*)d_in[2];
    const float* wout = (const float*)d_in[3];
    float* out = (float*)d_out;

    // 1) duplicate weights into padded (w,w) u64 layout in a device buffer
    prep_weights<<<(CW_ULLS + 255) / 256, 256>>>(win, ws, wout);

    // 2) stage into constant memory (async D2D memcpy: graph-capturable)
    void* wdup_addr = nullptr;
    cudaGetSymbolAddress(&wdup_addr, g_wdup);
    cudaMemcpyToSymbolAsync(cW, wdup_addr, CW_ULLS * sizeof(unsigned long long),
                            0, cudaMemcpyDeviceToDevice, 0);

    // 3) main compute: one thread per pixel pair
    const int pairs = BATCH * HWPIX / 2;   // 2,097,152
    simplenet_kernel<<<pairs / 256, 256>>>(x, out);
}